// round 10
// baseline (speedup 1.0000x reference)
#include <cuda_runtime.h>
#include <cuda_bf16.h>
#include <cstdint>

// ---------------- Problem constants ----------------
#define NNODES 50000
#define NEDGES 800000
#define ETOT   (NEDGES + NNODES)   // + self loops
#define NBLK   ((NNODES + 1023) / 1024)   // 49 scan blocks

// ---------------- Device scratch (no allocs allowed) ----------------
__device__ float g_xl[NNODES * 128];
__device__ float g_xr[NNODES * 128];
__device__ float g_h[NNODES * 128];      // layer activation ping buffer
__device__ unsigned g_xhi[NNODES * 64];  // X hi bf16x2 (k-pairs), row-major
__device__ unsigned g_xlo[NNODES * 64];  // X lo bf16x2
__device__ unsigned g_wbuf[4 * 128 * 64];// W frags: [l-hi][l-lo][r-hi][r-lo]
__device__ int   g_src[ETOT];
__device__ int   g_dst[ETOT];
__device__ int   g_csrc[ETOT];           // src ids sorted by dst (CSR)
__device__ int   g_rowptr[NNODES + 1];
__device__ int   g_deg[NNODES];
__device__ int   g_cnt[NNODES];
__device__ int   g_bsum[NBLK];
__device__ int   g_boff[NBLK];
__device__ int   g_is64;

// ---------------- mma.sync bf16 (sm_80+ PTX, family-wide) ----------------
__device__ __forceinline__ void mma_bf16(float* c, const unsigned* a,
                                         const unsigned* b) {
    asm volatile(
        "mma.sync.aligned.m16n8k16.row.col.f32.bf16.bf16.f32 "
        "{%0,%1,%2,%3}, {%4,%5,%6,%7}, {%8,%9}, {%0,%1,%2,%3};"
        : "+f"(c[0]), "+f"(c[1]), "+f"(c[2]), "+f"(c[3])
        : "r"(a[0]), "r"(a[1]), "r"(a[2]), "r"(a[3]), "r"(b[0]), "r"(b[1]));
}

// ---------------- zero counters + parallel dtype detect ----------------
__global__ void prep_kernel(const int* ei) {
    int i = blockIdx.x * blockDim.x + threadIdx.x;
    if (i < NNODES) { g_deg[i] = 0; g_cnt[i] = 0; }
    if (blockIdx.x == 0 && threadIdx.x < 32) {
        int nz = 0;
#pragma unroll
        for (int q = 0; q < 4; q++)
            nz |= ei[2 * (threadIdx.x * 4 + q) + 1];
        unsigned any = __ballot_sync(0xffffffffu, nz != 0);
        if (threadIdx.x == 0) g_is64 = (any == 0u);
    }
}

__global__ void canon_hist_kernel(const void* ei) {
    int i = blockIdx.x * blockDim.x + threadIdx.x;
    if (i >= ETOT) return;
    int s, d;
    if (i < NEDGES) {
        if (g_is64) {
            const long long* p = (const long long*)ei;
            s = (int)p[i];
            d = (int)p[NEDGES + i];
        } else {
            const int* p = (const int*)ei;
            s = p[i];
            d = p[NEDGES + i];
        }
    } else {
        s = d = i - NEDGES;
    }
    g_src[i] = s;
    g_dst[i] = d;
    atomicAdd(&g_deg[d], 1);
}

__global__ void scan1_kernel() {
    __shared__ int wtot[32];
    const int t = threadIdx.x, lane = t & 31, wid = t >> 5;
    const int gi = blockIdx.x * 1024 + t;
    int v = (gi < NNODES) ? g_deg[gi] : 0;
    int incl = v;
#pragma unroll
    for (int off = 1; off < 32; off <<= 1) {
        int x = __shfl_up_sync(0xffffffffu, incl, off);
        if (lane >= off) incl += x;
    }
    if (lane == 31) wtot[wid] = incl;
    __syncthreads();
    if (wid == 0) {
        int wv = wtot[lane];
        int wi = wv;
#pragma unroll
        for (int off = 1; off < 32; off <<= 1) {
            int x = __shfl_up_sync(0xffffffffu, wi, off);
            if (lane >= off) wi += x;
        }
        wtot[lane] = wi - wv;
    }
    __syncthreads();
    int excl = wtot[wid] + incl - v;
    if (gi < NNODES) g_rowptr[gi] = excl;
    if (t == 1023) g_bsum[blockIdx.x] = excl + v;
}

__global__ void scan2_kernel() {
    if (threadIdx.x == 0) {
        int t = 0;
#pragma unroll
        for (int ib = 0; ib < NBLK; ib++) {
            int v = g_bsum[ib];
            g_boff[ib] = t;
            t += v;
        }
        g_rowptr[NNODES] = t;
    }
}

__global__ void scan3_kernel() {
    int gi = blockIdx.x * 1024 + threadIdx.x;
    if (gi < NNODES && blockIdx.x > 0) g_rowptr[gi] += g_boff[blockIdx.x];
}

__global__ void scatter_kernel() {
    int i = blockIdx.x * blockDim.x + threadIdx.x;
    if (i >= ETOT) return;
    int d = g_dst[i];
    int pos = g_rowptr[d] + atomicAdd(&g_cnt[d], 1);
    g_csrc[pos] = g_src[i];
}

// ---------------- Split-bf16 conversion ----------------
// X [N,128] fp32 -> Xhi/Xlo row-major bf16x2 (u32[N][64], k-pairs)
__global__ void convert_x_kernel(const float* __restrict__ act) {
    int idx = blockIdx.x * blockDim.x + threadIdx.x;
    if (idx >= NNODES * 64) return;
    int r = idx >> 6, i = idx & 63;
    float2 v = *(const float2*)&act[r * 128 + i * 2];
    __nv_bfloat16 h0 = __float2bfloat16_rn(v.x);
    __nv_bfloat16 h1 = __float2bfloat16_rn(v.y);
    __nv_bfloat16 l0 = __float2bfloat16_rn(v.x - __bfloat162float(h0));
    __nv_bfloat16 l1 = __float2bfloat16_rn(v.y - __bfloat162float(h1));
    g_xhi[idx] = ((unsigned)__bfloat16_as_ushort(h1) << 16) | __bfloat16_as_ushort(h0);
    g_xlo[idx] = ((unsigned)__bfloat16_as_ushort(l1) << 16) | __bfloat16_as_ushort(l0);
}

// W [128,COLS] fp32 row-major -> per output col n, k-pair-packed u32[COLS][64]
template <int COLS>
__global__ void convert_w_kernel(const float* __restrict__ Wl,
                                 const float* __restrict__ Wr) {
    constexpr int TW = COLS * 64;
    int idx = blockIdx.x * blockDim.x + threadIdx.x;
    if (idx >= COLS * 64) return;
    int n = idx / 64, t = idx % 64;

    float a0 = Wl[(2 * t) * COLS + n], a1 = Wl[(2 * t + 1) * COLS + n];
    __nv_bfloat16 h0 = __float2bfloat16_rn(a0), h1 = __float2bfloat16_rn(a1);
    __nv_bfloat16 l0 = __float2bfloat16_rn(a0 - __bfloat162float(h0));
    __nv_bfloat16 l1 = __float2bfloat16_rn(a1 - __bfloat162float(h1));
    g_wbuf[0 * TW + idx] = ((unsigned)__bfloat16_as_ushort(h1) << 16) | __bfloat16_as_ushort(h0);
    g_wbuf[1 * TW + idx] = ((unsigned)__bfloat16_as_ushort(l1) << 16) | __bfloat16_as_ushort(l0);

    float b0 = Wr[(2 * t) * COLS + n], b1 = Wr[(2 * t + 1) * COLS + n];
    h0 = __float2bfloat16_rn(b0); h1 = __float2bfloat16_rn(b1);
    l0 = __float2bfloat16_rn(b0 - __bfloat162float(h0));
    l1 = __float2bfloat16_rn(b1 - __bfloat162float(h1));
    g_wbuf[2 * TW + idx] = ((unsigned)__bfloat16_as_ushort(h1) << 16) | __bfloat16_as_ushort(h0);
    g_wbuf[3 * TW + idx] = ((unsigned)__bfloat16_as_ushort(l1) << 16) | __bfloat16_as_ushort(l0);
}

// ---------------- HMMA dual GEMM: Yl = X@Wl, Yr = X@Wr ----------------
// 3xBF16 split: D = Xhi@Whi + Xhi@Wlo + Xlo@Whi, fp32 accumulate.
// CTA = 8 warps: warp w -> matrix (w>>2), rows blockIdx*64 + (w&3)*16.
template <int COLS>
__global__ __launch_bounds__(256) void gemm_mma_kernel(float* __restrict__ Yl,
                                                       float* __restrict__ Yr) {
    constexpr int NT = COLS / 8;
    const int tid = threadIdx.x;
    const int w = tid >> 5, lane = tid & 31;
    const int mat = w >> 2;
    const int row0 = blockIdx.x * 64 + (w & 3) * 16;
    const int g = lane >> 2, t = lane & 3;

    const unsigned* Wh = g_wbuf + mat * 2 * COLS * 64;
    const unsigned* Wlo = Wh + COLS * 64;

    const int r0 = row0 + g, r1 = row0 + g + 8;
    const int r0c = (r0 < NNODES) ? r0 : 0;
    const int r1c = (r1 < NNODES) ? r1 : 0;
    const unsigned* x0h = g_xhi + r0c * 64;
    const unsigned* x1h = g_xhi + r1c * 64;
    const unsigned* x0l = g_xlo + r0c * 64;
    const unsigned* x1l = g_xlo + r1c * 64;

    float acc[NT][4];
#pragma unroll
    for (int nt = 0; nt < NT; nt++)
#pragma unroll
        for (int j = 0; j < 4; j++) acc[nt][j] = 0.0f;

#pragma unroll
    for (int ks = 0; ks < 8; ks++) {
        const int ci = ks * 8 + t;
        unsigned ahi[4], alo[4];
        ahi[0] = x0h[ci];     ahi[1] = x1h[ci];
        ahi[2] = x0h[ci + 4]; ahi[3] = x1h[ci + 4];
        alo[0] = x0l[ci];     alo[1] = x1l[ci];
        alo[2] = x0l[ci + 4]; alo[3] = x1l[ci + 4];
#pragma unroll
        for (int nt = 0; nt < NT; nt++) {
            const int wrow = (nt * 8 + g) * 64 + ci;
            unsigned bhi[2] = { Wh[wrow],  Wh[wrow + 4] };
            unsigned blo[2] = { Wlo[wrow], Wlo[wrow + 4] };
            mma_bf16(acc[nt], ahi, bhi);
            mma_bf16(acc[nt], ahi, blo);
            mma_bf16(acc[nt], alo, bhi);
        }
    }

    float* Y = mat ? Yr : Yl;
#pragma unroll
    for (int nt = 0; nt < NT; nt++) {
        int c = nt * 8 + t * 2;
        if (r0 < NNODES)
            *(float2*)&Y[r0 * COLS + c] = make_float2(acc[nt][0], acc[nt][1]);
        if (r1 < NNODES)
            *(float2*)&Y[r1 * COLS + c] = make_float2(acc[nt][2], acc[nt][3]);
    }
}

// ---------------- CSR edge pass: 2-edge software-pipelined ----------------
template <int ROWF4>
__global__ void csr_edge_kernel(const float* __restrict__ att,
                                const float* __restrict__ bias,
                                float* __restrict__ out) {
    constexpr int NPW = 32 / ROWF4;
    int gwarp = (blockIdx.x * blockDim.x + threadIdx.x) >> 5;
    int lane = threadIdx.x & 31;
    int sub = lane / ROWF4;
    int l = lane % ROWF4;
    int d = gwarp * NPW + sub;
    if (d >= NNODES) return;

    const float4* xl4 = (const float4*)g_xl;
    float4 b = ((const float4*)g_xr)[d * ROWF4 + l];
    float4 w = ((const float4*)att)[l];

    float4 acc = make_float4(0.f, 0.f, 0.f, 0.f);
    float den = 0.f;

    int i = g_rowptr[d];
    const int end = g_rowptr[d + 1];

    int s0 = g_csrc[i];
    int s1 = (i + 1 < end) ? g_csrc[i + 1] : 0;
    float4 a0 = xl4[s0 * ROWF4 + l];
    float4 a1 = xl4[s1 * ROWF4 + l];

    while (i < end) {
        const int ni = i + 2;
        int t0 = (ni < end) ? g_csrc[ni] : 0;
        int t1 = (ni + 1 < end) ? g_csrc[ni + 1] : 0;
        float4 n0 = xl4[t0 * ROWF4 + l];
        float4 n1 = xl4[t1 * ROWF4 + l];

        float vx0 = a0.x + b.x, vy0 = a0.y + b.y, vz0 = a0.z + b.z, vw0 = a0.w + b.w;
        float vx1 = a1.x + b.x, vy1 = a1.y + b.y, vz1 = a1.z + b.z, vw1 = a1.w + b.w;
        vx0 = vx0 > 0.f ? vx0 : 0.2f * vx0;  vx1 = vx1 > 0.f ? vx1 : 0.2f * vx1;
        vy0 = vy0 > 0.f ? vy0 : 0.2f * vy0;  vy1 = vy1 > 0.f ? vy1 : 0.2f * vy1;
        vz0 = vz0 > 0.f ? vz0 : 0.2f * vz0;  vz1 = vz1 > 0.f ? vz1 : 0.2f * vz1;
        vw0 = vw0 > 0.f ? vw0 : 0.2f * vw0;  vw1 = vw1 > 0.f ? vw1 : 0.2f * vw1;
        float p0 = vx0 * w.x + vy0 * w.y + vz0 * w.z + vw0 * w.w;
        float p1 = vx1 * w.x + vy1 * w.y + vz1 * w.z + vw1 * w.w;

        p0 += __shfl_xor_sync(0xffffffffu, p0, 8);
        p1 += __shfl_xor_sync(0xffffffffu, p1, 8);
        p0 += __shfl_xor_sync(0xffffffffu, p0, 4);
        p1 += __shfl_xor_sync(0xffffffffu, p1, 4);
        p0 += __shfl_xor_sync(0xffffffffu, p0, 2);
        p1 += __shfl_xor_sync(0xffffffffu, p1, 2);
        p0 += __shfl_xor_sync(0xffffffffu, p0, 1);
        p1 += __shfl_xor_sync(0xffffffffu, p1, 1);

        float ex0 = __expf(p0);
        float ex1 = (i + 1 < end) ? __expf(p1) : 0.f;

        acc.x += ex0 * a0.x + ex1 * a1.x;
        acc.y += ex0 * a0.y + ex1 * a1.y;
        acc.z += ex0 * a0.z + ex1 * a1.z;
        acc.w += ex0 * a0.w + ex1 * a1.w;
        den += ex0 + ex1;

        a0 = n0; a1 = n1;
        i = ni;
    }

    float4 bi = ((const float4*)bias)[l];
    float inv = 1.0f / den;
    float4 o;
    o.x = acc.x * inv + bi.x;
    o.y = acc.y * inv + bi.y;
    o.z = acc.z * inv + bi.z;
    o.w = acc.w * inv + bi.w;
    o.x = o.x > 0.f ? o.x : (__expf(o.x) - 1.f);
    o.y = o.y > 0.f ? o.y : (__expf(o.y) - 1.f);
    o.z = o.z > 0.f ? o.z : (__expf(o.z) - 1.f);
    o.w = o.w > 0.f ? o.w : (__expf(o.w) - 1.f);
    ((float4*)out)[d * ROWF4 + l] = o;
}

// ---------------- Layer driver ----------------
template <int COLS>
static void run_layer(const float* in, const float* Wl, const float* Wr,
                      const float* att, const float* bias, float* out,
                      float* d_xl, float* d_xr) {
    constexpr int ROWF4 = COLS / 4;
    constexpr int NPW = 32 / ROWF4;
    convert_x_kernel<<<(NNODES * 64 + 255) / 256, 256>>>(in);
    convert_w_kernel<COLS><<<(COLS * 64 + 255) / 256, 256>>>(Wl, Wr);
    gemm_mma_kernel<COLS><<<(NNODES + 63) / 64, 256>>>(d_xl, d_xr);
    int nwarps = (NNODES + NPW - 1) / NPW;
    csr_edge_kernel<ROWF4><<<(nwarps * 32 + 255) / 256, 256>>>(att, bias, out);
}

// ---------------- Entry point ----------------
extern "C" void kernel_launch(void* const* d_in, const int* in_sizes, int n_in,
                              void* d_out, int out_size) {
    const float* x    = (const float*)d_in[0];
    const void*  ei   = d_in[1];
    const float* W1l  = (const float*)d_in[2];
    const float* W1r  = (const float*)d_in[3];
    const float* att1 = (const float*)d_in[4];
    const float* b1   = (const float*)d_in[5];
    const float* W2l  = (const float*)d_in[6];
    const float* W2r  = (const float*)d_in[7];
    const float* att2 = (const float*)d_in[8];
    const float* b2   = (const float*)d_in[9];
    const float* W3l  = (const float*)d_in[10];
    const float* W3r  = (const float*)d_in[11];
    const float* att3 = (const float*)d_in[12];
    const float* b3   = (const float*)d_in[13];
    float* out = (float*)d_out;

    float *d_xl, *d_xr, *d_h;
    cudaGetSymbolAddress((void**)&d_xl, g_xl);
    cudaGetSymbolAddress((void**)&d_xr, g_xr);
    cudaGetSymbolAddress((void**)&d_h,  g_h);

    // one-time preprocessing: dtype canon + CSR build (dst-sorted)
    prep_kernel<<<(NNODES + 255) / 256, 256>>>((const int*)ei);
    canon_hist_kernel<<<(ETOT + 255) / 256, 256>>>(ei);
    scan1_kernel<<<NBLK, 1024>>>();
    scan2_kernel<<<1, 32>>>();
    scan3_kernel<<<NBLK, 1024>>>();
    scatter_kernel<<<(ETOT + 255) / 256, 256>>>();

    run_layer<128>(x,   W1l, W1r, att1, b1, d_h, d_xl, d_xr);
    run_layer<128>(d_h, W2l, W2r, att2, b2, d_h, d_xl, d_xr);
    run_layer<64>(d_h,  W3l, W3r, att3, b3, out, d_xl, d_xr);
}

// round 11
// speedup vs baseline: 1.6990x; 1.6990x over previous
#include <cuda_runtime.h>
#include <cuda_bf16.h>
#include <cstdint>

// ---------------- Problem constants ----------------
#define NNODES 50000
#define NEDGES 800000
#define ETOT   (NEDGES + NNODES)   // + self loops
#define NBLK   ((NNODES + 1023) / 1024)   // 49 scan blocks
#define NT16   (NNODES / 16)              // 3125 16-row fragment tiles (exact)

typedef unsigned long long u64;

// ---------------- Device scratch (no allocs allowed) ----------------
__device__ float g_xl[NNODES * 128];
__device__ float g_xr[NNODES * 128];
__device__ float g_h[NNODES * 128];      // layer activation ping buffer
__device__ uint4 g_xfh[NT16 * 8 * 32];   // X hi A-fragments [tile16][ks][lane]
__device__ uint4 g_xfl[NT16 * 8 * 32];   // X lo A-fragments
__device__ u64   g_wf[4 * 8 * 16 * 32];  // W B-frags: [l-hi][l-lo][r-hi][r-lo]
__device__ int   g_src[ETOT];
__device__ int   g_dst[ETOT];
__device__ int   g_csrc[ETOT];           // src ids sorted by dst (CSR)
__device__ int   g_rowptr[NNODES + 1];
__device__ int   g_deg[NNODES];
__device__ int   g_cnt[NNODES];
__device__ int   g_bsum[NBLK];
__device__ int   g_boff[NBLK];
__device__ int   g_is64;

// ---------------- mma.sync bf16 (sm_80+ PTX, family-wide) ----------------
__device__ __forceinline__ void mma_bf16(float* c, const uint4& a, u64 b) {
    unsigned b0 = (unsigned)b, b1 = (unsigned)(b >> 32);
    asm volatile(
        "mma.sync.aligned.m16n8k16.row.col.f32.bf16.bf16.f32 "
        "{%0,%1,%2,%3}, {%4,%5,%6,%7}, {%8,%9}, {%0,%1,%2,%3};"
        : "+f"(c[0]), "+f"(c[1]), "+f"(c[2]), "+f"(c[3])
        : "r"(a.x), "r"(a.y), "r"(a.z), "r"(a.w), "r"(b0), "r"(b1));
}

__device__ __forceinline__ unsigned pack_hi(float x, float y,
                                            unsigned& lo_out) {
    __nv_bfloat16 hx = __float2bfloat16_rn(x);
    __nv_bfloat16 hy = __float2bfloat16_rn(y);
    __nv_bfloat16 lx = __float2bfloat16_rn(x - __bfloat162float(hx));
    __nv_bfloat16 ly = __float2bfloat16_rn(y - __bfloat162float(hy));
    lo_out = ((unsigned)__bfloat16_as_ushort(ly) << 16) | __bfloat16_as_ushort(lx);
    return ((unsigned)__bfloat16_as_ushort(hy) << 16) | __bfloat16_as_ushort(hx);
}

// ---------------- zero counters + parallel dtype detect ----------------
__global__ void prep_kernel(const int* ei) {
    int i = blockIdx.x * blockDim.x + threadIdx.x;
    if (i < NNODES) { g_deg[i] = 0; g_cnt[i] = 0; }
    if (blockIdx.x == 0 && threadIdx.x < 32) {
        int nz = 0;
#pragma unroll
        for (int q = 0; q < 4; q++)
            nz |= ei[2 * (threadIdx.x * 4 + q) + 1];
        unsigned any = __ballot_sync(0xffffffffu, nz != 0);
        if (threadIdx.x == 0) g_is64 = (any == 0u);
    }
}

__global__ void canon_hist_kernel(const void* ei) {
    int i = blockIdx.x * blockDim.x + threadIdx.x;
    if (i >= ETOT) return;
    int s, d;
    if (i < NEDGES) {
        if (g_is64) {
            const long long* p = (const long long*)ei;
            s = (int)p[i];
            d = (int)p[NEDGES + i];
        } else {
            const int* p = (const int*)ei;
            s = p[i];
            d = p[NEDGES + i];
        }
    } else {
        s = d = i - NEDGES;
    }
    g_src[i] = s;
    g_dst[i] = d;
    atomicAdd(&g_deg[d], 1);
}

__global__ void scan1_kernel() {
    __shared__ int wtot[32];
    const int t = threadIdx.x, lane = t & 31, wid = t >> 5;
    const int gi = blockIdx.x * 1024 + t;
    int v = (gi < NNODES) ? g_deg[gi] : 0;
    int incl = v;
#pragma unroll
    for (int off = 1; off < 32; off <<= 1) {
        int x = __shfl_up_sync(0xffffffffu, incl, off);
        if (lane >= off) incl += x;
    }
    if (lane == 31) wtot[wid] = incl;
    __syncthreads();
    if (wid == 0) {
        int wv = wtot[lane];
        int wi = wv;
#pragma unroll
        for (int off = 1; off < 32; off <<= 1) {
            int x = __shfl_up_sync(0xffffffffu, wi, off);
            if (lane >= off) wi += x;
        }
        wtot[lane] = wi - wv;
    }
    __syncthreads();
    int excl = wtot[wid] + incl - v;
    if (gi < NNODES) g_rowptr[gi] = excl;
    if (t == 1023) g_bsum[blockIdx.x] = excl + v;
}

__global__ void scan2_kernel() {
    if (threadIdx.x == 0) {
        int t = 0;
#pragma unroll
        for (int ib = 0; ib < NBLK; ib++) {
            int v = g_bsum[ib];
            g_boff[ib] = t;
            t += v;
        }
        g_rowptr[NNODES] = t;
    }
}

__global__ void scan3_kernel() {
    int gi = blockIdx.x * 1024 + threadIdx.x;
    if (gi < NNODES && blockIdx.x > 0) g_rowptr[gi] += g_boff[blockIdx.x];
}

__global__ void scatter_kernel() {
    int i = blockIdx.x * blockDim.x + threadIdx.x;
    if (i >= ETOT) return;
    int d = g_dst[i];
    int pos = g_rowptr[d] + atomicAdd(&g_cnt[d], 1);
    g_csrc[pos] = g_src[i];
}

// ---------------- X -> A-fragment-major hi/lo conversion ----------------
// One thread per (tile16, ks, lane): writes one uint4 hi + one uint4 lo,
// exactly the m16n8k16 A fragment for that lane.
__global__ void convert_x_kernel(const float* __restrict__ act) {
    int idx = blockIdx.x * blockDim.x + threadIdx.x;
    if (idx >= NT16 * 8 * 32) return;
    int lane = idx & 31;
    int ks = (idx >> 5) & 7;
    int tile = idx >> 8;
    int g = lane >> 2, t = lane & 3;
    int r0 = tile * 16 + g, r1 = r0 + 8;
    int c0 = (ks * 8 + t) * 2;         // k-pair ci
    int c1 = c0 + 8;                   // k-pair ci+4

    float2 v0 = *(const float2*)&act[r0 * 128 + c0];
    float2 v1 = *(const float2*)&act[r1 * 128 + c0];
    float2 v2 = *(const float2*)&act[r0 * 128 + c1];
    float2 v3 = *(const float2*)&act[r1 * 128 + c1];

    uint4 hi, lo;
    hi.x = pack_hi(v0.x, v0.y, lo.x);
    hi.y = pack_hi(v1.x, v1.y, lo.y);
    hi.z = pack_hi(v2.x, v2.y, lo.z);
    hi.w = pack_hi(v3.x, v3.y, lo.w);
    g_xfh[idx] = hi;
    g_xfl[idx] = lo;
}

// W [128,COLS] -> B-fragment-major u64s: part stride 8*NT*32.
// One thread per (ks, nt, lane); writes l-hi, l-lo, r-hi, r-lo.
template <int COLS>
__global__ void convert_w_kernel(const float* __restrict__ Wl,
                                 const float* __restrict__ Wr) {
    constexpr int NT = COLS / 8;
    constexpr int PART = 8 * NT * 32;
    int idx = blockIdx.x * blockDim.x + threadIdx.x;
    if (idx >= PART) return;
    int lane = idx & 31;
    int nt = (idx >> 5) % NT;
    int ks = (idx >> 5) / NT;
    int g = lane >> 2, t = lane & 3;
    int n = nt * 8 + g;
    int k0 = (ks * 8 + t) * 2;
    int k1 = k0 + 8;

    unsigned lo0, lo1;
    unsigned hi0 = pack_hi(Wl[k0 * COLS + n], Wl[(k0 + 1) * COLS + n], lo0);
    unsigned hi1 = pack_hi(Wl[k1 * COLS + n], Wl[(k1 + 1) * COLS + n], lo1);
    g_wf[0 * PART + idx] = ((u64)hi1 << 32) | hi0;
    g_wf[1 * PART + idx] = ((u64)lo1 << 32) | lo0;

    hi0 = pack_hi(Wr[k0 * COLS + n], Wr[(k0 + 1) * COLS + n], lo0);
    hi1 = pack_hi(Wr[k1 * COLS + n], Wr[(k1 + 1) * COLS + n], lo1);
    g_wf[2 * PART + idx] = ((u64)hi1 << 32) | hi0;
    g_wf[3 * PART + idx] = ((u64)lo1 << 32) | lo0;
}

// ---------------- HMMA dual GEMM (fragment-major, coalesced) ----------------
// 3xBF16 split: D = Xhi@Whi + Xhi@Wlo + Xlo@Whi, fp32 accumulate.
// CTA = 8 warps: warp w -> matrix (w>>2), 16-row tile blockIdx*4 + (w&3).
template <int COLS>
__global__ __launch_bounds__(256) void gemm_mma_kernel(float* __restrict__ Yl,
                                                       float* __restrict__ Yr) {
    constexpr int NT = COLS / 8;
    constexpr int PART = 8 * NT * 32;
    const int tid = threadIdx.x;
    const int w = tid >> 5, lane = tid & 31;
    const int mat = w >> 2;
    const int tile = blockIdx.x * 4 + (w & 3);
    if (tile >= NT16) return;
    const int g = lane >> 2, t = lane & 3;

    const u64* Wh = g_wf + mat * 2 * PART;
    const u64* Wlo = Wh + PART;
    const uint4* Ah = g_xfh + tile * 256;
    const uint4* Al = g_xfl + tile * 256;

    float acc[NT][4];
#pragma unroll
    for (int nt = 0; nt < NT; nt++)
#pragma unroll
        for (int j = 0; j < 4; j++) acc[nt][j] = 0.0f;

#pragma unroll
    for (int ks = 0; ks < 8; ks++) {
        uint4 ahi = Ah[ks * 32 + lane];
        uint4 alo = Al[ks * 32 + lane];
        const u64* whk = Wh + (ks * NT) * 32 + lane;
        const u64* wlk = Wlo + (ks * NT) * 32 + lane;
#pragma unroll
        for (int nt = 0; nt < NT; nt++) {
            u64 bh = whk[nt * 32];
            u64 bl = wlk[nt * 32];
            mma_bf16(acc[nt], ahi, bh);
            mma_bf16(acc[nt], ahi, bl);
            mma_bf16(acc[nt], alo, bh);
        }
    }

    float* Y = mat ? Yr : Yl;
    const int r0 = tile * 16 + g, r1 = r0 + 8;
#pragma unroll
    for (int nt = 0; nt < NT; nt++) {
        int c = nt * 8 + t * 2;
        *(float2*)&Y[r0 * COLS + c] = make_float2(acc[nt][0], acc[nt][1]);
        *(float2*)&Y[r1 * COLS + c] = make_float2(acc[nt][2], acc[nt][3]);
    }
}

// ---------------- CSR edge pass: 2-edge software-pipelined ----------------
template <int ROWF4>
__global__ void csr_edge_kernel(const float* __restrict__ att,
                                const float* __restrict__ bias,
                                float* __restrict__ out) {
    constexpr int NPW = 32 / ROWF4;
    int gwarp = (blockIdx.x * blockDim.x + threadIdx.x) >> 5;
    int lane = threadIdx.x & 31;
    int sub = lane / ROWF4;
    int l = lane % ROWF4;
    int d = gwarp * NPW + sub;
    if (d >= NNODES) return;

    const float4* xl4 = (const float4*)g_xl;
    float4 b = ((const float4*)g_xr)[d * ROWF4 + l];
    float4 w = ((const float4*)att)[l];

    float4 acc = make_float4(0.f, 0.f, 0.f, 0.f);
    float den = 0.f;

    int i = g_rowptr[d];
    const int end = g_rowptr[d + 1];

    int s0 = g_csrc[i];
    int s1 = (i + 1 < end) ? g_csrc[i + 1] : 0;
    float4 a0 = xl4[s0 * ROWF4 + l];
    float4 a1 = xl4[s1 * ROWF4 + l];

    while (i < end) {
        const int ni = i + 2;
        int t0 = (ni < end) ? g_csrc[ni] : 0;
        int t1 = (ni + 1 < end) ? g_csrc[ni + 1] : 0;
        float4 n0 = xl4[t0 * ROWF4 + l];
        float4 n1 = xl4[t1 * ROWF4 + l];

        float vx0 = a0.x + b.x, vy0 = a0.y + b.y, vz0 = a0.z + b.z, vw0 = a0.w + b.w;
        float vx1 = a1.x + b.x, vy1 = a1.y + b.y, vz1 = a1.z + b.z, vw1 = a1.w + b.w;
        vx0 = vx0 > 0.f ? vx0 : 0.2f * vx0;  vx1 = vx1 > 0.f ? vx1 : 0.2f * vx1;
        vy0 = vy0 > 0.f ? vy0 : 0.2f * vy0;  vy1 = vy1 > 0.f ? vy1 : 0.2f * vy1;
        vz0 = vz0 > 0.f ? vz0 : 0.2f * vz0;  vz1 = vz1 > 0.f ? vz1 : 0.2f * vz1;
        vw0 = vw0 > 0.f ? vw0 : 0.2f * vw0;  vw1 = vw1 > 0.f ? vw1 : 0.2f * vw1;
        float p0 = vx0 * w.x + vy0 * w.y + vz0 * w.z + vw0 * w.w;
        float p1 = vx1 * w.x + vy1 * w.y + vz1 * w.z + vw1 * w.w;

        p0 += __shfl_xor_sync(0xffffffffu, p0, 8);
        p1 += __shfl_xor_sync(0xffffffffu, p1, 8);
        p0 += __shfl_xor_sync(0xffffffffu, p0, 4);
        p1 += __shfl_xor_sync(0xffffffffu, p1, 4);
        p0 += __shfl_xor_sync(0xffffffffu, p0, 2);
        p1 += __shfl_xor_sync(0xffffffffu, p1, 2);
        p0 += __shfl_xor_sync(0xffffffffu, p0, 1);
        p1 += __shfl_xor_sync(0xffffffffu, p1, 1);

        float ex0 = __expf(p0);
        float ex1 = (i + 1 < end) ? __expf(p1) : 0.f;

        acc.x += ex0 * a0.x + ex1 * a1.x;
        acc.y += ex0 * a0.y + ex1 * a1.y;
        acc.z += ex0 * a0.z + ex1 * a1.z;
        acc.w += ex0 * a0.w + ex1 * a1.w;
        den += ex0 + ex1;

        a0 = n0; a1 = n1;
        i = ni;
    }

    float4 bi = ((const float4*)bias)[l];
    float inv = 1.0f / den;
    float4 o;
    o.x = acc.x * inv + bi.x;
    o.y = acc.y * inv + bi.y;
    o.z = acc.z * inv + bi.z;
    o.w = acc.w * inv + bi.w;
    o.x = o.x > 0.f ? o.x : (__expf(o.x) - 1.f);
    o.y = o.y > 0.f ? o.y : (__expf(o.y) - 1.f);
    o.z = o.z > 0.f ? o.z : (__expf(o.z) - 1.f);
    o.w = o.w > 0.f ? o.w : (__expf(o.w) - 1.f);
    ((float4*)out)[d * ROWF4 + l] = o;
}

// ---------------- Layer driver ----------------
template <int COLS>
static void run_layer(const float* in, const float* Wl, const float* Wr,
                      const float* att, const float* bias, float* out,
                      float* d_xl, float* d_xr) {
    constexpr int ROWF4 = COLS / 4;
    constexpr int NPW = 32 / ROWF4;
    constexpr int PART = 8 * (COLS / 8) * 32;
    convert_x_kernel<<<(NT16 * 256 + 255) / 256, 256>>>(in);
    convert_w_kernel<COLS><<<(PART + 255) / 256, 256>>>(Wl, Wr);
    gemm_mma_kernel<COLS><<<(NT16 + 3) / 4, 256>>>(d_xl, d_xr);
    int nwarps = (NNODES + NPW - 1) / NPW;
    csr_edge_kernel<ROWF4><<<(nwarps * 32 + 255) / 256, 256>>>(att, bias, out);
}

// ---------------- Entry point ----------------
extern "C" void kernel_launch(void* const* d_in, const int* in_sizes, int n_in,
                              void* d_out, int out_size) {
    const float* x    = (const float*)d_in[0];
    const void*  ei   = d_in[1];
    const float* W1l  = (const float*)d_in[2];
    const float* W1r  = (const float*)d_in[3];
    const float* att1 = (const float*)d_in[4];
    const float* b1   = (const float*)d_in[5];
    const float* W2l  = (const float*)d_in[6];
    const float* W2r  = (const float*)d_in[7];
    const float* att2 = (const float*)d_in[8];
    const float* b2   = (const float*)d_in[9];
    const float* W3l  = (const float*)d_in[10];
    const float* W3r  = (const float*)d_in[11];
    const float* att3 = (const float*)d_in[12];
    const float* b3   = (const float*)d_in[13];
    float* out = (float*)d_out;

    float *d_xl, *d_xr, *d_h;
    cudaGetSymbolAddress((void**)&d_xl, g_xl);
    cudaGetSymbolAddress((void**)&d_xr, g_xr);
    cudaGetSymbolAddress((void**)&d_h,  g_h);

    // one-time preprocessing: dtype canon + CSR build (dst-sorted)
    prep_kernel<<<(NNODES + 255) / 256, 256>>>((const int*)ei);
    canon_hist_kernel<<<(ETOT + 255) / 256, 256>>>(ei);
    scan1_kernel<<<NBLK, 1024>>>();
    scan2_kernel<<<1, 32>>>();
    scan3_kernel<<<NBLK, 1024>>>();
    scatter_kernel<<<(ETOT + 255) / 256, 256>>>();

    run_layer<128>(x,   W1l, W1r, att1, b1, d_h, d_xl, d_xr);
    run_layer<128>(d_h, W2l, W2r, att2, b2, d_h, d_xl, d_xr);
    run_layer<64>(d_h,  W3l, W3r, att3, b3, out, d_xl, d_xr);
}